// round 1
// baseline (speedup 1.0000x reference)
#include <cuda_runtime.h>
#include <cstdint>

// Problem constants
#define BATCH  8
#define SEQ    1024
#define DMODEL 1024
#define NHEAD  16
#define DK     64
#define DV     64
#define DOUT   1024

// d_out layout assumption: [out (B*N*DOUT floats)] then [attn (B*A*N*N floats)]
#define ATTN_OFF ((size_t)BATCH * SEQ * DOUT)   // 8388608

// ---------------------------------------------------------------------------
// Scratch (static device arrays; no allocation allowed)
// ---------------------------------------------------------------------------
__device__ float g_Qp[(size_t)BATCH * NHEAD * SEQ * DK];   // [ba][n][d]
__device__ float g_Kp[(size_t)BATCH * NHEAD * SEQ * DK];   // [ba][m][d]
__device__ float g_Vt[(size_t)BATCH * NHEAD * DV * SEQ];   // [ba][j][m]  (V transposed)
__device__ float g_ne[(size_t)BATCH * SEQ * NHEAD * DV];   // [b][n][a*64+j]
__device__ float g_WqT[DMODEL * DMODEL];                   // [col][row] of W_q
__device__ float g_WkT[DMODEL * DMODEL];
__device__ float g_WvT[DMODEL * DMODEL];
__device__ float g_WoT[DMODEL * DMODEL];

// ---------------------------------------------------------------------------
// Helpers
// ---------------------------------------------------------------------------
__device__ __forceinline__ uint32_t f2tf(float f) {
    uint32_t r;
    asm("cvt.rna.tf32.f32 %0, %1;" : "=r"(r) : "f"(f));
    return r;
}

// ---------------------------------------------------------------------------
// Generic tf32 GEMM core.
//   C[M,N] = A[M,K] (row-major, lda) @ B (col-major: element (k,n) at Bg[n*ldb+k])
// Block tile BM x BN x 32, 256 threads (8 warps, 4x2 warp grid).
// MODE selects the epilogue scatter:
//   0: Q/K projection scatter -> [ba][n][d]
//   1: V projection transposed scatter -> [ba][j][m]
//   2: plain row-major, ldc=1024 (attn tile, base pre-offset per ba)
//   3: new_emb scatter using ba -> [b][n][a*64+j]
//   4: plain row-major, ldc=1024 (final out)
// ---------------------------------------------------------------------------
template<int BM, int BN, int MODE>
__device__ __forceinline__ void gemm_core(
    const float* __restrict__ Ag, int lda,
    const float* __restrict__ Bg, int ldb,
    int Ktot, float* __restrict__ Cb,
    int mtile, int ntile, int ba,
    uint32_t* smem)
{
    constexpr int BK = 32;
    constexpr int AS = BK + 4;          // padded stride (36): conflict-free frag LDS
    constexpr int MI = (BM / 4) / 16;   // mma tiles in M per warp
    constexpr int NI = (BN / 2) / 8;    // mma tiles in N per warp

    uint32_t* As = smem;                // [BM][AS]
    uint32_t* Bs = smem + BM * AS;      // [BN][AS]

    const int tid  = threadIdx.x;
    const int warp = tid >> 5;
    const int lane = tid & 31;
    const int wmb  = (warp >> 1) * (BM / 4);
    const int wnb  = (warp & 1) * (BN / 2);
    const int g    = lane >> 2;   // groupID
    const int tg   = lane & 3;    // threadID_in_group

    float acc[MI][NI][4];
    #pragma unroll
    for (int mi = 0; mi < MI; mi++)
        #pragma unroll
        for (int ni = 0; ni < NI; ni++)
            #pragma unroll
            for (int e = 0; e < 4; e++) acc[mi][ni][e] = 0.0f;

    constexpr int A_ITERS = BM * (BK / 4) / 256;   // float4 loads per thread
    constexpr int B_ITERS = BN * (BK / 4) / 256;

    const int nkt = Ktot / BK;
    for (int kt = 0; kt < nkt; kt++) {
        // Stage A tile (row-major, float4, cvt to tf32)
        #pragma unroll
        for (int it = 0; it < A_ITERS; it++) {
            int i   = tid + it * 256;
            int row = i >> 3;
            int c4  = (i & 7) * 4;
            const float4 v = *reinterpret_cast<const float4*>(
                Ag + (size_t)(mtile * BM + row) * lda + kt * BK + c4);
            As[row * AS + c4 + 0] = f2tf(v.x);
            As[row * AS + c4 + 1] = f2tf(v.y);
            As[row * AS + c4 + 2] = f2tf(v.z);
            As[row * AS + c4 + 3] = f2tf(v.w);
        }
        // Stage B tile (col-major: contiguous along k, float4)
        #pragma unroll
        for (int it = 0; it < B_ITERS; it++) {
            int i  = tid + it * 256;
            int n  = i >> 3;
            int c4 = (i & 7) * 4;
            const float4 v = *reinterpret_cast<const float4*>(
                Bg + (size_t)(ntile * BN + n) * ldb + kt * BK + c4);
            Bs[n * AS + c4 + 0] = f2tf(v.x);
            Bs[n * AS + c4 + 1] = f2tf(v.y);
            Bs[n * AS + c4 + 2] = f2tf(v.z);
            Bs[n * AS + c4 + 3] = f2tf(v.w);
        }
        __syncthreads();

        #pragma unroll
        for (int ks = 0; ks < BK / 8; ks++) {
            const int k0 = ks * 8;
            uint32_t af[MI][4];
            #pragma unroll
            for (int mi = 0; mi < MI; mi++) {
                int r = wmb + mi * 16 + g;
                af[mi][0] = As[(r    ) * AS + k0 + tg    ];
                af[mi][1] = As[(r + 8) * AS + k0 + tg    ];
                af[mi][2] = As[(r    ) * AS + k0 + tg + 4];
                af[mi][3] = As[(r + 8) * AS + k0 + tg + 4];
            }
            #pragma unroll
            for (int ni = 0; ni < NI; ni++) {
                int n = wnb + ni * 8 + g;
                uint32_t b0 = Bs[n * AS + k0 + tg    ];
                uint32_t b1 = Bs[n * AS + k0 + tg + 4];
                #pragma unroll
                for (int mi = 0; mi < MI; mi++) {
                    asm volatile(
                        "mma.sync.aligned.m16n8k8.row.col.f32.tf32.tf32.f32 "
                        "{%0,%1,%2,%3}, {%4,%5,%6,%7}, {%8,%9}, {%0,%1,%2,%3};\n"
                        : "+f"(acc[mi][ni][0]), "+f"(acc[mi][ni][1]),
                          "+f"(acc[mi][ni][2]), "+f"(acc[mi][ni][3])
                        : "r"(af[mi][0]), "r"(af[mi][1]),
                          "r"(af[mi][2]), "r"(af[mi][3]),
                          "r"(b0), "r"(b1));
                }
            }
        }
        __syncthreads();
    }

    // Epilogue
    #pragma unroll
    for (int mi = 0; mi < MI; mi++) {
        #pragma unroll
        for (int ni = 0; ni < NI; ni++) {
            #pragma unroll
            for (int e = 0; e < 4; e++) {
                int r = mtile * BM + wmb + mi * 16 + g + ((e >= 2) ? 8 : 0);
                int c = ntile * BN + wnb + ni * 8 + tg * 2 + (e & 1);
                float v = acc[mi][ni][e];
                size_t idx;
                if (MODE == 0) {
                    // [ba][n][d]: ba = (r/1024)*16 + c/64 ; n = r%1024 ; d = c%64
                    idx = (size_t)((r >> 10) * NHEAD + (c >> 6)) * ((size_t)SEQ * 64)
                        + (size_t)(r & 1023) * 64 + (c & 63);
                } else if (MODE == 1) {
                    // [ba][j][m]
                    idx = (size_t)((r >> 10) * NHEAD + (c >> 6)) * ((size_t)SEQ * 64)
                        + (size_t)(c & 63) * SEQ + (r & 1023);
                } else if (MODE == 3) {
                    // [b][n][a*64+j], r = token within ba
                    int b = ba >> 4, a = ba & 15;
                    idx = ((size_t)(b * SEQ + r)) * (NHEAD * DV) + a * 64 + c;
                } else {
                    idx = (size_t)r * 1024 + c;
                }
                Cb[idx] = v;
            }
        }
    }
}

// ---------------------------------------------------------------------------
// Kernels
// ---------------------------------------------------------------------------
__global__ void k_transpose(const float* __restrict__ in, int which) {
    __shared__ float t[32][33];
    float* out = (which == 0) ? g_WqT : (which == 1) ? g_WkT
               : (which == 2) ? g_WvT : g_WoT;
    int xi = blockIdx.x * 32 + threadIdx.x;
    int yi = blockIdx.y * 32 + threadIdx.y;
    #pragma unroll
    for (int j = 0; j < 32; j += 8)
        t[threadIdx.y + j][threadIdx.x] = in[(size_t)(yi + j) * DMODEL + xi];
    __syncthreads();
    int xo = blockIdx.y * 32 + threadIdx.x;
    int yo = blockIdx.x * 32 + threadIdx.y;
    #pragma unroll
    for (int j = 0; j < 32; j += 8)
        out[(size_t)(yo + j) * DMODEL + xo] = t[threadIdx.x][threadIdx.y + j];
}

__global__ void __launch_bounds__(256, 1)
k_proj(const float* __restrict__ q, const float* __restrict__ k,
       const float* __restrict__ v) {
    __shared__ uint32_t smem[2 * 128 * 36];
    int z = blockIdx.z;
    const float* A  = (z == 0) ? q : (z == 1) ? k : v;
    const float* Bc = (z == 0) ? g_WqT : (z == 1) ? g_WkT : g_WvT;
    if (z == 0)
        gemm_core<128, 128, 0>(A, DMODEL, Bc, DMODEL, DMODEL, g_Qp,
                               blockIdx.x, blockIdx.y, 0, smem);
    else if (z == 1)
        gemm_core<128, 128, 0>(A, DMODEL, Bc, DMODEL, DMODEL, g_Kp,
                               blockIdx.x, blockIdx.y, 0, smem);
    else
        gemm_core<128, 128, 1>(A, DMODEL, Bc, DMODEL, DMODEL, g_Vt,
                               blockIdx.x, blockIdx.y, 0, smem);
}

__global__ void __launch_bounds__(256, 1)
k_qk(float* __restrict__ out) {
    __shared__ uint32_t smem[2 * 128 * 36];
    int ba = blockIdx.z;
    const float* Qa = g_Qp + (size_t)ba * SEQ * DK;
    const float* Ka = g_Kp + (size_t)ba * SEQ * DK;   // col-major B: (d, m) at Ka[m*64+d]
    float* Cb = out + ATTN_OFF + (size_t)ba * SEQ * SEQ;
    gemm_core<128, 128, 2>(Qa, DK, Ka, DK, DK, Cb,
                           blockIdx.x, blockIdx.y, ba, smem);
}

__global__ void __launch_bounds__(256, 1)
k_pv(const float* __restrict__ out_as_in) {
    __shared__ uint32_t smem[128 * 36 + 64 * 36];
    int ba = blockIdx.z;
    const float* Aa = out_as_in + ATTN_OFF + (size_t)ba * SEQ * SEQ;  // attn [n][m]
    const float* Ba = g_Vt + (size_t)ba * DV * SEQ;   // col-major B: (m, j) at Ba[j*1024+m]
    gemm_core<128, 64, 3>(Aa, SEQ, Ba, SEQ, SEQ, g_ne,
                          blockIdx.x, 0, ba, smem);
}

__global__ void __launch_bounds__(256, 1)
k_out(float* __restrict__ out) {
    __shared__ uint32_t smem[2 * 128 * 36];
    gemm_core<128, 128, 4>(g_ne, NHEAD * DV, g_WoT, NHEAD * DV, NHEAD * DV, out,
                           blockIdx.x, blockIdx.y, 0, smem);
}

// ---------------------------------------------------------------------------
// Launch
// ---------------------------------------------------------------------------
extern "C" void kernel_launch(void* const* d_in, const int* in_sizes, int n_in,
                              void* d_out, int out_size) {
    const float* q  = (const float*)d_in[0];
    const float* k  = (const float*)d_in[1];
    const float* v  = (const float*)d_in[2];
    const float* Wq = (const float*)d_in[3];
    const float* Wk = (const float*)d_in[4];
    const float* Wv = (const float*)d_in[5];
    const float* Wo = (const float*)d_in[6];
    float* out = (float*)d_out;
    (void)in_sizes; (void)n_in; (void)out_size;

    dim3 tb(32, 8), tg(32, 32);
    k_transpose<<<tg, tb>>>(Wq, 0);
    k_transpose<<<tg, tb>>>(Wk, 1);
    k_transpose<<<tg, tb>>>(Wv, 2);
    k_transpose<<<tg, tb>>>(Wo, 3);

    k_proj<<<dim3(64, 8, 3), 256>>>(q, k, v);                 // Q,K,V projections
    k_qk  <<<dim3(8, 8, BATCH * NHEAD), 256>>>(out);          // attn = Q K^T (written to d_out)
    k_pv  <<<dim3(8, 1, BATCH * NHEAD), 256>>>(out);          // new_emb = attn V
    k_out <<<dim3(64, 8), 256>>>(out);                        // final projection
}

// round 2
// speedup vs baseline: 1.4753x; 1.4753x over previous
#include <cuda_runtime.h>
#include <cstdint>

#define BATCH  8
#define SEQ    1024
#define DMODEL 1024
#define NHEAD  16
#define DK     64
#define DV     64
#define DOUT   1024

#define ATTN_OFF ((size_t)BATCH * SEQ * DOUT)   // out tensor first, then attn

// ---------------------------------------------------------------------------
// Scratch
// ---------------------------------------------------------------------------
__device__ __align__(128) float g_Qp[(size_t)BATCH * NHEAD * SEQ * DK];   // [ba][n][d]
__device__ __align__(128) float g_Kp[(size_t)BATCH * NHEAD * SEQ * DK];   // [ba][m][d]
__device__ __align__(128) float g_Vp[(size_t)BATCH * NHEAD * SEQ * DV];   // [ba][m][j]
__device__ __align__(128) float g_ne[(size_t)BATCH * SEQ * NHEAD * DV];   // [b][n][a*64+j]
__device__ __align__(128) float g_WqT[DMODEL * DMODEL];                   // [col][row]
__device__ __align__(128) float g_WkT[DMODEL * DMODEL];
__device__ __align__(128) float g_WvT[DMODEL * DMODEL];
__device__ __align__(128) float g_WoT[DMODEL * DMODEL];

// ---------------------------------------------------------------------------
// Helpers
// ---------------------------------------------------------------------------
__device__ __forceinline__ uint32_t f2tf(float f) {
    uint32_t r;
    asm("cvt.rna.tf32.f32 %0, %1;" : "=r"(r) : "f"(f));
    return r;
}
__device__ __forceinline__ uint32_t smem_u32(const void* p) {
    return (uint32_t)__cvta_generic_to_shared(p);
}
__device__ __forceinline__ void cp16(uint32_t s, const float* g) {
    asm volatile("cp.async.cg.shared.global [%0], [%1], 16;" :: "r"(s), "l"(g));
}
__device__ __forceinline__ void cp_commit() {
    asm volatile("cp.async.commit_group;");
}
template<int N> __device__ __forceinline__ void cp_wait() {
    asm volatile("cp.async.wait_group %0;" :: "n"(N));
}
__device__ __forceinline__ void mma_tf32(float* c, uint32_t a0, uint32_t a1,
                                         uint32_t a2, uint32_t a3,
                                         uint32_t b0, uint32_t b1) {
    asm volatile(
        "mma.sync.aligned.m16n8k8.row.col.f32.tf32.tf32.f32 "
        "{%0,%1,%2,%3}, {%4,%5,%6,%7}, {%8,%9}, {%0,%1,%2,%3};\n"
        : "+f"(c[0]), "+f"(c[1]), "+f"(c[2]), "+f"(c[3])
        : "r"(a0), "r"(a1), "r"(a2), "r"(a3), "r"(b0), "r"(b1));
}

// ---------------------------------------------------------------------------
// Pipelined tf32 GEMM core (cp.async double-buffered).
//   C[M,N] = A[M,K] (row-major, lda) @ B (col-major: (k,n) at Bg[n*ldb+k])
// 256 threads, 4x2 warp grid, BM=BN=128, BK=32.
// MODE 0: head scatter -> [ba][n][d] ; MODE 4: row-major ldc=1024
// ---------------------------------------------------------------------------
template<int MODE>
__device__ __forceinline__ void gemm_core2(
    const float* __restrict__ Ag, int lda,
    const float* __restrict__ Bg, int ldb,
    int Ktot, float* __restrict__ Cb,
    int mtile, int ntile, float* smem)
{
    constexpr int BM = 128, BN = 128, BK = 32, AS = 36;
    constexpr int MI = 2, NI = 8;
    constexpr int STAGE = (BM + BN) * AS;   // floats per stage

    float* As = smem;              // + stage*STAGE
    float* Bs = smem + BM * AS;

    const int tid  = threadIdx.x;
    const int warp = tid >> 5;
    const int lane = tid & 31;
    const int wmb  = (warp >> 1) * 32;
    const int wnb  = (warp & 1) * 64;
    const int g    = lane >> 2;
    const int tg   = lane & 3;

    float acc[MI][NI][4];
    #pragma unroll
    for (int mi = 0; mi < MI; mi++)
        #pragma unroll
        for (int ni = 0; ni < NI; ni++)
            #pragma unroll
            for (int e = 0; e < 4; e++) acc[mi][ni][e] = 0.0f;

    const int nkt = Ktot / BK;

    auto issue = [&](int kt, int st) {
        float* Ad = As + st * STAGE;
        float* Bd = Bs + st * STAGE;
        #pragma unroll
        for (int it = 0; it < 4; it++) {          // 128 rows x 8 chunks / 256 thr
            int i = tid + it * 256;
            int row = i >> 3, c4 = (i & 7) * 4;
            cp16(smem_u32(Ad + row * AS + c4),
                 Ag + (size_t)(mtile * BM + row) * lda + kt * BK + c4);
        }
        #pragma unroll
        for (int it = 0; it < 4; it++) {
            int i = tid + it * 256;
            int row = i >> 3, c4 = (i & 7) * 4;
            cp16(smem_u32(Bd + row * AS + c4),
                 Bg + (size_t)(ntile * BN + row) * ldb + kt * BK + c4);
        }
        cp_commit();
    };

    issue(0, 0);
    for (int kt = 0; kt < nkt; kt++) {
        if (kt + 1 < nkt) issue(kt + 1, (kt + 1) & 1);
        else cp_commit();
        cp_wait<1>();
        __syncthreads();

        const float* Ac = As + (kt & 1) * STAGE;
        const float* Bc = Bs + (kt & 1) * STAGE;

        #pragma unroll
        for (int ks = 0; ks < 4; ks++) {
            const int k0 = ks * 8;
            uint32_t af[MI][4];
            #pragma unroll
            for (int mi = 0; mi < MI; mi++) {
                int r = wmb + mi * 16 + g;
                af[mi][0] = f2tf(Ac[(r    ) * AS + k0 + tg    ]);
                af[mi][1] = f2tf(Ac[(r + 8) * AS + k0 + tg    ]);
                af[mi][2] = f2tf(Ac[(r    ) * AS + k0 + tg + 4]);
                af[mi][3] = f2tf(Ac[(r + 8) * AS + k0 + tg + 4]);
            }
            #pragma unroll
            for (int ni = 0; ni < NI; ni++) {
                int n = wnb + ni * 8 + g;
                uint32_t b0 = f2tf(Bc[n * AS + k0 + tg    ]);
                uint32_t b1 = f2tf(Bc[n * AS + k0 + tg + 4]);
                #pragma unroll
                for (int mi = 0; mi < MI; mi++)
                    mma_tf32(acc[mi][ni], af[mi][0], af[mi][1], af[mi][2], af[mi][3], b0, b1);
            }
        }
        __syncthreads();
    }

    // Epilogue (float2 stores)
    #pragma unroll
    for (int mi = 0; mi < MI; mi++) {
        #pragma unroll
        for (int ni = 0; ni < NI; ni++) {
            #pragma unroll
            for (int h = 0; h < 2; h++) {     // h=0: rows g, h=1: rows g+8
                int r = mtile * BM + wmb + mi * 16 + g + h * 8;
                int c = ntile * BN + wnb + ni * 8 + tg * 2;
                float2 v = make_float2(acc[mi][ni][h * 2], acc[mi][ni][h * 2 + 1]);
                size_t idx;
                if (MODE == 0) {
                    idx = (size_t)((r >> 10) * NHEAD + (c >> 6)) * ((size_t)SEQ * 64)
                        + (size_t)(r & 1023) * 64 + (c & 63);
                } else {
                    idx = (size_t)r * 1024 + c;
                }
                *reinterpret_cast<float2*>(Cb + idx) = v;
            }
        }
    }
}

// ---------------------------------------------------------------------------
// Kernels
// ---------------------------------------------------------------------------
__global__ void k_transpose(const float* __restrict__ wq, const float* __restrict__ wk,
                            const float* __restrict__ wv, const float* __restrict__ wo) {
    __shared__ float t[32][33];
    int z = blockIdx.z;
    const float* in = (z == 0) ? wq : (z == 1) ? wk : (z == 2) ? wv : wo;
    float* outp     = (z == 0) ? g_WqT : (z == 1) ? g_WkT : (z == 2) ? g_WvT : g_WoT;
    int xi = blockIdx.x * 32 + threadIdx.x;
    int yi = blockIdx.y * 32 + threadIdx.y;
    #pragma unroll
    for (int j = 0; j < 32; j += 8)
        t[threadIdx.y + j][threadIdx.x] = in[(size_t)(yi + j) * DMODEL + xi];
    __syncthreads();
    int xo = blockIdx.y * 32 + threadIdx.x;
    int yo = blockIdx.x * 32 + threadIdx.y;
    #pragma unroll
    for (int j = 0; j < 32; j += 8)
        outp[(size_t)(yo + j) * DMODEL + xo] = t[threadIdx.x][threadIdx.y + j];
}

__global__ void __launch_bounds__(256, 2)
k_proj(const float* __restrict__ q, const float* __restrict__ k,
       const float* __restrict__ v) {
    extern __shared__ float dsm[];
    int z = blockIdx.z;
    if (z == 0)
        gemm_core2<0>(q, DMODEL, g_WqT, DMODEL, DMODEL, g_Qp, blockIdx.x, blockIdx.y, dsm);
    else if (z == 1)
        gemm_core2<0>(k, DMODEL, g_WkT, DMODEL, DMODEL, g_Kp, blockIdx.x, blockIdx.y, dsm);
    else
        gemm_core2<0>(v, DMODEL, g_WvT, DMODEL, DMODEL, g_Vp, blockIdx.x, blockIdx.y, dsm);
}

__global__ void __launch_bounds__(256, 2)
k_out(float* __restrict__ out) {
    extern __shared__ float dsm[];
    gemm_core2<4>(g_ne, NHEAD * DV, g_WoT, NHEAD * DV, NHEAD * DV, out,
                  blockIdx.x, blockIdx.y, dsm);
}

// Fused attention: per (mtile, ba) block computes S = Q K^T for 128 Q-rows,
// writes S to the attn output, and accumulates O = S V in registers.
// 8 warps x 16 rows each; K/V streamed in 64-row steps, cp.async double-buffered.
#define KLD 68              // K smem row stride (floats)
#define VLD 72              // V smem row stride (floats)
#define KST (64 * KLD)
#define VST (64 * VLD)

__global__ void __launch_bounds__(256, 2)
k_attn(float* __restrict__ out) {
    extern __shared__ float dsm[];
    float* Ks  = dsm;               // [2][64][KLD]
    float* Vsb = dsm + 2 * KST;     // [2][64][VLD]

    const int tid  = threadIdx.x;
    const int warp = tid >> 5;
    const int lane = tid & 31;
    const int g    = lane >> 2;
    const int tg   = lane & 3;
    const int mtile = blockIdx.x;
    const int ba    = blockIdx.y;

    const float* Kg = g_Kp + (size_t)ba * SEQ * DK;
    const float* Vg = g_Vp + (size_t)ba * SEQ * DV;

    // Q fragments: 16 rows per warp, K=64 -> 8 k-steps, held in regs.
    uint32_t qf[8][4];
    {
        const float* Qg = g_Qp + ((size_t)ba * SEQ + mtile * 128 + warp * 16) * DK;
        #pragma unroll
        for (int ks = 0; ks < 8; ks++) {
            qf[ks][0] = f2tf(Qg[(size_t)(g    ) * DK + ks * 8 + tg    ]);
            qf[ks][1] = f2tf(Qg[(size_t)(g + 8) * DK + ks * 8 + tg    ]);
            qf[ks][2] = f2tf(Qg[(size_t)(g    ) * DK + ks * 8 + tg + 4]);
            qf[ks][3] = f2tf(Qg[(size_t)(g + 8) * DK + ks * 8 + tg + 4]);
        }
    }

    float oacc[8][4];
    #pragma unroll
    for (int jf = 0; jf < 8; jf++)
        #pragma unroll
        for (int e = 0; e < 4; e++) oacc[jf][e] = 0.0f;

    float* ap = out + ATTN_OFF + (size_t)ba * SEQ * SEQ
              + (size_t)(mtile * 128 + warp * 16) * SEQ;

    auto issueKV = [&](int t, int st) {
        const int m0 = t * 64;
        #pragma unroll
        for (int it = 0; it < 4; it++) {      // 64 rows x 16 chunks / 256 thr
            int i = tid + it * 256;
            int row = i >> 4, c4 = (i & 15) * 4;
            cp16(smem_u32(Ks + st * KST + row * KLD + c4),
                 Kg + (size_t)(m0 + row) * DK + c4);
        }
        #pragma unroll
        for (int it = 0; it < 4; it++) {
            int i = tid + it * 256;
            int row = i >> 4, c4 = (i & 15) * 4;
            cp16(smem_u32(Vsb + st * VST + row * VLD + c4),
                 Vg + (size_t)(m0 + row) * DV + c4);
        }
        cp_commit();
    };

    issueKV(0, 0);
    for (int t = 0; t < 16; t++) {
        if (t + 1 < 16) issueKV(t + 1, (t + 1) & 1);
        else cp_commit();
        cp_wait<1>();
        __syncthreads();

        const float* Kc = Ks  + (t & 1) * KST;
        const float* Vc = Vsb + (t & 1) * VST;

        // S = Q K^T for this 64-col step
        float sacc[8][4];
        #pragma unroll
        for (int ni = 0; ni < 8; ni++)
            #pragma unroll
            for (int e = 0; e < 4; e++) sacc[ni][e] = 0.0f;

        #pragma unroll
        for (int ks = 0; ks < 8; ks++) {
            #pragma unroll
            for (int ni = 0; ni < 8; ni++) {
                uint32_t b0 = f2tf(Kc[(ni * 8 + g) * KLD + ks * 8 + tg    ]);
                uint32_t b1 = f2tf(Kc[(ni * 8 + g) * KLD + ks * 8 + tg + 4]);
                mma_tf32(sacc[ni], qf[ks][0], qf[ks][1], qf[ks][2], qf[ks][3], b0, b1);
            }
        }

        // write S tile to attn output
        #pragma unroll
        for (int ni = 0; ni < 8; ni++) {
            *reinterpret_cast<float2*>(ap + (size_t)g * SEQ + t * 64 + ni * 8 + 2 * tg)
                = make_float2(sacc[ni][0], sacc[ni][1]);
            *reinterpret_cast<float2*>(ap + (size_t)(g + 8) * SEQ + t * 64 + ni * 8 + 2 * tg)
                = make_float2(sacc[ni][2], sacc[ni][3]);
        }

        // O += S V : shuffle-convert acc fragments to A-operand fragments
        const int sbase = (lane & ~3) | (tg >> 1);
        const bool odd  = tg & 1;
        #pragma unroll
        for (int kg = 0; kg < 8; kg++) {
            float v0 = __shfl_sync(0xffffffffu, sacc[kg][0], sbase);
            float v1 = __shfl_sync(0xffffffffu, sacc[kg][1], sbase);
            float w0 = __shfl_sync(0xffffffffu, sacc[kg][0], sbase + 2);
            float w1 = __shfl_sync(0xffffffffu, sacc[kg][1], sbase + 2);
            float v2 = __shfl_sync(0xffffffffu, sacc[kg][2], sbase);
            float v3 = __shfl_sync(0xffffffffu, sacc[kg][3], sbase);
            float w2 = __shfl_sync(0xffffffffu, sacc[kg][2], sbase + 2);
            float w3 = __shfl_sync(0xffffffffu, sacc[kg][3], sbase + 2);
            uint32_t a0 = f2tf(odd ? v1 : v0);
            uint32_t a2 = f2tf(odd ? w1 : w0);
            uint32_t a1 = f2tf(odd ? v3 : v2);
            uint32_t a3 = f2tf(odd ? w3 : w2);
            #pragma unroll
            for (int jf = 0; jf < 8; jf++) {
                uint32_t b0 = f2tf(Vc[(kg * 8 + tg    ) * VLD + jf * 8 + g]);
                uint32_t b1 = f2tf(Vc[(kg * 8 + tg + 4) * VLD + jf * 8 + g]);
                mma_tf32(oacc[jf], a0, a1, a2, a3, b0, b1);
            }
        }
        __syncthreads();
    }

    // O epilogue -> g_ne [b][n][a*64 + j]
    {
        const int b = ba >> 4, a = ba & 15;
        float* ne = g_ne + ((size_t)(b * SEQ) + mtile * 128 + warp * 16) * (NHEAD * DV)
                  + a * 64;
        #pragma unroll
        for (int jf = 0; jf < 8; jf++) {
            *reinterpret_cast<float2*>(ne + (size_t)g * (NHEAD * DV) + jf * 8 + 2 * tg)
                = make_float2(oacc[jf][0], oacc[jf][1]);
            *reinterpret_cast<float2*>(ne + (size_t)(g + 8) * (NHEAD * DV) + jf * 8 + 2 * tg)
                = make_float2(oacc[jf][2], oacc[jf][3]);
        }
    }
}

// ---------------------------------------------------------------------------
// Launch
// ---------------------------------------------------------------------------
extern "C" void kernel_launch(void* const* d_in, const int* in_sizes, int n_in,
                              void* d_out, int out_size) {
    const float* q  = (const float*)d_in[0];
    const float* k  = (const float*)d_in[1];
    const float* v  = (const float*)d_in[2];
    const float* Wq = (const float*)d_in[3];
    const float* Wk = (const float*)d_in[4];
    const float* Wv = (const float*)d_in[5];
    const float* Wo = (const float*)d_in[6];
    float* out = (float*)d_out;
    (void)in_sizes; (void)n_in; (void)out_size;

    const int GEMM_SMEM = 2 * 256 * 36 * 4;          // 73728 B
    const int ATTN_SMEM = (2 * KST + 2 * VST) * 4;   // 71680 B
    cudaFuncSetAttribute(k_proj, cudaFuncAttributeMaxDynamicSharedMemorySize, GEMM_SMEM);
    cudaFuncSetAttribute(k_out,  cudaFuncAttributeMaxDynamicSharedMemorySize, GEMM_SMEM);
    cudaFuncSetAttribute(k_attn, cudaFuncAttributeMaxDynamicSharedMemorySize, ATTN_SMEM);

    k_transpose<<<dim3(32, 32, 4), dim3(32, 8)>>>(Wq, Wk, Wv, Wo);
    k_proj<<<dim3(64, 8, 3), 256, GEMM_SMEM>>>(q, k, v);
    k_attn<<<dim3(8, BATCH * NHEAD), 256, ATTN_SMEM>>>(out);
    k_out<<<dim3(64, 8), 256, GEMM_SMEM>>>(out);
}

// round 3
// speedup vs baseline: 3.0602x; 2.0744x over previous
#include <cuda_runtime.h>
#include <cuda_fp16.h>
#include <cstdint>

#define BATCH  8
#define SEQ    1024
#define DMODEL 1024
#define NHEAD  16
#define DK     64
#define DV     64
#define DOUT   1024
#define ATTN_OFF ((size_t)BATCH * SEQ * DOUT)

// ---------------------------------------------------------------------------
// f16 scratch
// ---------------------------------------------------------------------------
__device__ __align__(128) __half g_qh[(size_t)BATCH * SEQ * DMODEL];
__device__ __align__(128) __half g_kh[(size_t)BATCH * SEQ * DMODEL];
__device__ __align__(128) __half g_vh[(size_t)BATCH * SEQ * DMODEL];
__device__ __align__(128) __half g_Qh[(size_t)BATCH * NHEAD * SEQ * DK];  // [ba][n][d]
__device__ __align__(128) __half g_Kh[(size_t)BATCH * NHEAD * SEQ * DK];  // [ba][m][d]
__device__ __align__(128) __half g_Vh[(size_t)BATCH * NHEAD * SEQ * DV];  // [ba][m][j]
__device__ __align__(128) __half g_neh[(size_t)BATCH * SEQ * NHEAD * DV]; // [b][n][a*64+j]
__device__ __align__(128) __half g_WqT[DMODEL * DMODEL];  // [out_col][in]
__device__ __align__(128) __half g_WkT[DMODEL * DMODEL];
__device__ __align__(128) __half g_WvT[DMODEL * DMODEL];
__device__ __align__(128) __half g_WoT[DMODEL * DMODEL];

// ---------------------------------------------------------------------------
// Helpers
// ---------------------------------------------------------------------------
__device__ __forceinline__ uint32_t smem_u32(const void* p) {
    return (uint32_t)__cvta_generic_to_shared(p);
}
__device__ __forceinline__ void cp16(uint32_t s, const void* g) {
    asm volatile("cp.async.cg.shared.global [%0], [%1], 16;" :: "r"(s), "l"(g));
}
__device__ __forceinline__ void cp_commit() {
    asm volatile("cp.async.commit_group;");
}
template<int N> __device__ __forceinline__ void cp_wait() {
    asm volatile("cp.async.wait_group %0;" :: "n"(N));
}
#define LDSM4(r0,r1,r2,r3,addr) \
    asm volatile("ldmatrix.sync.aligned.m8n8.x4.shared.b16 {%0,%1,%2,%3}, [%4];" \
        : "=r"(r0),"=r"(r1),"=r"(r2),"=r"(r3) : "r"(addr))
#define LDSM4T(r0,r1,r2,r3,addr) \
    asm volatile("ldmatrix.sync.aligned.m8n8.x4.trans.shared.b16 {%0,%1,%2,%3}, [%4];" \
        : "=r"(r0),"=r"(r1),"=r"(r2),"=r"(r3) : "r"(addr))
__device__ __forceinline__ void mma16816(float* c, const uint32_t* a,
                                         uint32_t b0, uint32_t b1) {
    asm volatile(
        "mma.sync.aligned.m16n8k16.row.col.f32.f16.f16.f32 "
        "{%0,%1,%2,%3}, {%4,%5,%6,%7}, {%8,%9}, {%0,%1,%2,%3};"
        : "+f"(c[0]), "+f"(c[1]), "+f"(c[2]), "+f"(c[3])
        : "r"(a[0]), "r"(a[1]), "r"(a[2]), "r"(a[3]), "r"(b0), "r"(b1));
}
__device__ __forceinline__ uint32_t packh2(float lo, float hi) {
    __half2 h = __floats2half2_rn(lo, hi);
    return *reinterpret_cast<uint32_t*>(&h);
}

// ---------------------------------------------------------------------------
// fp16 GEMM core: C[M,N] = A[M,K] @ B(col-major, [n][k] rows), BM=BN=128, BK=32.
// 4-stage cp.async pipeline, single barrier per k-step, ldmatrix fragments.
// MODE 0: f16 head-scatter -> [ba][n][d]. MODE 4: f32 row-major ldc=1024.
// ---------------------------------------------------------------------------
template<int MODE>
__device__ __forceinline__ void hgemm(
    const __half* __restrict__ Ag, int lda,
    const __half* __restrict__ Bg, int ldb,
    int nkt, void* Cb, int mtile, int ntile, __half* smem)
{
    constexpr int LD = 40;            // padded row stride (halves); 80B, 16B-aligned
    constexpr int TS = 128 * LD;      // halves per tile
    constexpr int STG = 2 * TS;       // A+B per stage

    const int tid = threadIdx.x, warp = tid >> 5, lane = tid & 31;
    const int wmb = (warp >> 1) * 32, wnb = (warp & 1) * 64;
    const int g = lane >> 2, tg = lane & 3;

    float acc[2][8][4];
    #pragma unroll
    for (int mi = 0; mi < 2; mi++)
        #pragma unroll
        for (int ni = 0; ni < 8; ni++)
            #pragma unroll
            for (int e = 0; e < 4; e++) acc[mi][ni][e] = 0.0f;

    auto issue = [&](int kt) {
        __half* S = smem + (kt & 3) * STG;
        #pragma unroll
        for (int it = 0; it < 2; it++) {
            int i = tid + it * 256;
            int row = i >> 2, c8 = (i & 3) * 8;
            cp16(smem_u32(S + row * LD + c8),
                 Ag + (size_t)(mtile * 128 + row) * lda + kt * 32 + c8);
        }
        #pragma unroll
        for (int it = 0; it < 2; it++) {
            int i = tid + it * 256;
            int row = i >> 2, c8 = (i & 3) * 8;
            cp16(smem_u32(S + TS + row * LD + c8),
                 Bg + (size_t)(ntile * 128 + row) * ldb + kt * 32 + c8);
        }
        cp_commit();
    };

    issue(0); issue(1);
    for (int kt = 0; kt < nkt; kt++) {
        if (kt + 2 < nkt) issue(kt + 2); else cp_commit();
        cp_wait<2>();
        __syncthreads();

        uint32_t smA = smem_u32(smem + (kt & 3) * STG);
        uint32_t smB = smA + TS * 2;

        #pragma unroll
        for (int ks = 0; ks < 2; ks++) {
            uint32_t a[2][4];
            #pragma unroll
            for (int mi = 0; mi < 2; mi++) {
                uint32_t ad = smA + (((wmb + mi * 16 + (lane & 15)) * LD)
                                     + ks * 16 + (lane >> 4) * 8) * 2;
                LDSM4(a[mi][0], a[mi][1], a[mi][2], a[mi][3], ad);
            }
            #pragma unroll
            for (int np = 0; np < 4; np++) {
                int n = wnb + np * 16 + (lane & 7) + ((lane >> 4) & 1) * 8;
                int koff = ks * 16 + ((lane >> 3) & 1) * 8;
                uint32_t b0, b1, b2, b3;
                LDSM4(b0, b1, b2, b3, smB + (n * LD + koff) * 2);
                #pragma unroll
                for (int mi = 0; mi < 2; mi++) {
                    mma16816(acc[mi][2 * np],     a[mi], b0, b1);
                    mma16816(acc[mi][2 * np + 1], a[mi], b2, b3);
                }
            }
        }
    }

    // Epilogue
    #pragma unroll
    for (int mi = 0; mi < 2; mi++) {
        #pragma unroll
        for (int ni = 0; ni < 8; ni++) {
            #pragma unroll
            for (int h = 0; h < 2; h++) {
                int r = mtile * 128 + wmb + mi * 16 + g + h * 8;
                int c = ntile * 128 + wnb + ni * 8 + 2 * tg;
                float v0 = acc[mi][ni][h * 2], v1 = acc[mi][ni][h * 2 + 1];
                if (MODE == 0) {
                    size_t idx = (size_t)((r >> 10) * NHEAD + (c >> 6)) * ((size_t)SEQ * 64)
                               + (size_t)(r & 1023) * 64 + (c & 63);
                    *reinterpret_cast<__half2*>((__half*)Cb + idx) = __floats2half2_rn(v0, v1);
                } else {
                    *reinterpret_cast<float2*>((float*)Cb + (size_t)r * 1024 + c)
                        = make_float2(v0, v1);
                }
            }
        }
    }
}

// ---------------------------------------------------------------------------
// Small kernels: input f32->f16 convert; weight transpose+convert
// ---------------------------------------------------------------------------
__global__ void k_cvt(const float* __restrict__ q, const float* __restrict__ k,
                      const float* __restrict__ v) {
    int z = blockIdx.z;
    const float* src = (z == 0) ? q : (z == 1) ? k : v;
    __half* dst      = (z == 0) ? g_qh : (z == 1) ? g_kh : g_vh;
    size_t i = ((size_t)blockIdx.x * 256 + threadIdx.x) * 8;
    float4 a = *reinterpret_cast<const float4*>(src + i);
    float4 b = *reinterpret_cast<const float4*>(src + i + 4);
    __half2 h0 = __floats2half2_rn(a.x, a.y), h1 = __floats2half2_rn(a.z, a.w);
    __half2 h2 = __floats2half2_rn(b.x, b.y), h3 = __floats2half2_rn(b.z, b.w);
    uint4 o;
    o.x = *reinterpret_cast<uint32_t*>(&h0); o.y = *reinterpret_cast<uint32_t*>(&h1);
    o.z = *reinterpret_cast<uint32_t*>(&h2); o.w = *reinterpret_cast<uint32_t*>(&h3);
    *reinterpret_cast<uint4*>(dst + i) = o;
}

__global__ void k_transpose(const float* __restrict__ wq, const float* __restrict__ wk,
                            const float* __restrict__ wv, const float* __restrict__ wo) {
    __shared__ float t[32][33];
    int z = blockIdx.z;
    const float* in = (z == 0) ? wq : (z == 1) ? wk : (z == 2) ? wv : wo;
    __half* outp    = (z == 0) ? g_WqT : (z == 1) ? g_WkT : (z == 2) ? g_WvT : g_WoT;
    int xi = blockIdx.x * 32 + threadIdx.x;
    int yi = blockIdx.y * 32 + threadIdx.y;
    #pragma unroll
    for (int j = 0; j < 32; j += 8)
        t[threadIdx.y + j][threadIdx.x] = in[(size_t)(yi + j) * DMODEL + xi];
    __syncthreads();
    int xo = blockIdx.y * 32 + threadIdx.x;
    int yo = blockIdx.x * 32 + threadIdx.y;
    #pragma unroll
    for (int j = 0; j < 32; j += 8)
        outp[(size_t)(yo + j) * DMODEL + xo] = __float2half_rn(t[threadIdx.x][threadIdx.y + j]);
}

// ---------------------------------------------------------------------------
// GEMM kernels
// ---------------------------------------------------------------------------
__global__ void __launch_bounds__(256, 2)
k_proj() {
    extern __shared__ __half hsm[];
    int z = blockIdx.z;
    if (z == 0)
        hgemm<0>(g_qh, DMODEL, g_WqT, DMODEL, 32, g_Qh, blockIdx.x, blockIdx.y, hsm);
    else if (z == 1)
        hgemm<0>(g_kh, DMODEL, g_WkT, DMODEL, 32, g_Kh, blockIdx.x, blockIdx.y, hsm);
    else
        hgemm<0>(g_vh, DMODEL, g_WvT, DMODEL, 32, g_Vh, blockIdx.x, blockIdx.y, hsm);
}

__global__ void __launch_bounds__(256, 2)
k_out(float* __restrict__ out) {
    extern __shared__ __half hsm[];
    hgemm<4>(g_neh, NHEAD * DV, g_WoT, NHEAD * DV, 32, out, blockIdx.x, blockIdx.y, hsm);
}

// ---------------------------------------------------------------------------
// Fused attention (f16): S = Q K^T (written f32 to attn out), O = S V in regs.
// Per block: 128 Q rows x one ba. KV streamed in 64-row tiles, 4-stage pipeline.
// ---------------------------------------------------------------------------
#define QLD 72
#define KVLD 72
#define KTS (64 * KVLD)
#define STGA (2 * KTS)

__global__ void __launch_bounds__(256, 2)
k_attn(float* __restrict__ out) {
    extern __shared__ __half hsm[];
    __half* Qs = hsm;                    // [128][72]
    __half* KV = hsm + 128 * QLD;        // [4 stages][K 64x72 | V 64x72]

    const int tid = threadIdx.x, warp = tid >> 5, lane = tid & 31;
    const int g = lane >> 2, tg = lane & 3;
    const int mtile = blockIdx.x, ba = blockIdx.y;

    const __half* Kg = g_Kh + (size_t)ba * SEQ * DK;
    const __half* Vg = g_Vh + (size_t)ba * SEQ * DV;

    // Stage Q (group 0)
    {
        const __half* Qg = g_Qh + ((size_t)ba * SEQ + mtile * 128) * DK;
        #pragma unroll
        for (int it = 0; it < 4; it++) {
            int i = tid + it * 256;
            int row = i >> 3, c8 = (i & 7) * 8;
            cp16(smem_u32(Qs + row * QLD + c8), Qg + (size_t)row * DK + c8);
        }
        cp_commit();
    }

    auto issueKV = [&](int t) {
        __half* S = KV + (t & 3) * STGA;
        int m0 = t * 64;
        #pragma unroll
        for (int it = 0; it < 2; it++) {
            int i = tid + it * 256;
            int row = i >> 3, c8 = (i & 7) * 8;
            cp16(smem_u32(S + row * KVLD + c8), Kg + (size_t)(m0 + row) * DK + c8);
        }
        #pragma unroll
        for (int it = 0; it < 2; it++) {
            int i = tid + it * 256;
            int row = i >> 3, c8 = (i & 7) * 8;
            cp16(smem_u32(S + KTS + row * KVLD + c8), Vg + (size_t)(m0 + row) * DV + c8);
        }
        cp_commit();
    };

    issueKV(0); issueKV(1);

    uint32_t qf[4][4];
    float oacc[8][4];
    #pragma unroll
    for (int jf = 0; jf < 8; jf++)
        #pragma unroll
        for (int e = 0; e < 4; e++) oacc[jf][e] = 0.0f;

    float* ap = out + ATTN_OFF + (size_t)ba * SEQ * SEQ
              + (size_t)(mtile * 128 + warp * 16) * SEQ;

    for (int t = 0; t < 16; t++) {
        if (t + 2 < 16) issueKV(t + 2); else cp_commit();
        cp_wait<2>();
        __syncthreads();

        if (t == 0) {
            uint32_t qb = smem_u32(Qs);
            #pragma unroll
            for (int ks = 0; ks < 4; ks++) {
                uint32_t ad = qb + ((warp * 16 + (lane & 15)) * QLD
                                    + ks * 16 + (lane >> 4) * 8) * 2;
                LDSM4(qf[ks][0], qf[ks][1], qf[ks][2], qf[ks][3], ad);
            }
        }

        uint32_t kb = smem_u32(KV + (t & 3) * STGA);
        uint32_t vb = kb + KTS * 2;

        // S = Q K^T for this 64-col block
        float sacc[8][4];
        #pragma unroll
        for (int ni = 0; ni < 8; ni++)
            #pragma unroll
            for (int e = 0; e < 4; e++) sacc[ni][e] = 0.0f;

        #pragma unroll
        for (int ks = 0; ks < 4; ks++) {
            #pragma unroll
            for (int np = 0; np < 4; np++) {
                int n = np * 16 + (lane & 7) + ((lane >> 4) & 1) * 8;
                int koff = ks * 16 + ((lane >> 3) & 1) * 8;
                uint32_t b0, b1, b2, b3;
                LDSM4(b0, b1, b2, b3, kb + (n * KVLD + koff) * 2);
                mma16816(sacc[2 * np],     qf[ks], b0, b1);
                mma16816(sacc[2 * np + 1], qf[ks], b2, b3);
            }
        }

        // Write S (f32) to attn output
        #pragma unroll
        for (int ni = 0; ni < 8; ni++) {
            *reinterpret_cast<float2*>(ap + (size_t)g * SEQ + t * 64 + ni * 8 + 2 * tg)
                = make_float2(sacc[ni][0], sacc[ni][1]);
            *reinterpret_cast<float2*>(ap + (size_t)(g + 8) * SEQ + t * 64 + ni * 8 + 2 * tg)
                = make_float2(sacc[ni][2], sacc[ni][3]);
        }

        // O += S V  (A-frags come straight from sacc: no shuffles)
        #pragma unroll
        for (int kk = 0; kk < 4; kk++) {
            uint32_t a[4];
            a[0] = packh2(sacc[2 * kk][0],     sacc[2 * kk][1]);
            a[1] = packh2(sacc[2 * kk][2],     sacc[2 * kk][3]);
            a[2] = packh2(sacc[2 * kk + 1][0], sacc[2 * kk + 1][1]);
            a[3] = packh2(sacc[2 * kk + 1][2], sacc[2 * kk + 1][3]);
            #pragma unroll
            for (int jp = 0; jp < 4; jp++) {
                int krow = kk * 16 + (lane & 7) + ((lane >> 3) & 1) * 8;
                int coff = jp * 16 + (lane >> 4) * 8;
                uint32_t b0, b1, b2, b3;
                LDSM4T(b0, b1, b2, b3, vb + (krow * KVLD + coff) * 2);
                mma16816(oacc[2 * jp],     a, b0, b1);
                mma16816(oacc[2 * jp + 1], a, b2, b3);
            }
        }
    }

    // O epilogue -> g_neh [b][n][a*64 + j] (f16)
    {
        const int b = ba >> 4, a = ba & 15;
        __half* ne = g_neh + ((size_t)(b * SEQ) + mtile * 128 + warp * 16) * (NHEAD * DV)
                   + a * 64;
        #pragma unroll
        for (int jf = 0; jf < 8; jf++) {
            *reinterpret_cast<__half2*>(ne + (size_t)g * (NHEAD * DV) + jf * 8 + 2 * tg)
                = __floats2half2_rn(oacc[jf][0], oacc[jf][1]);
            *reinterpret_cast<__half2*>(ne + (size_t)(g + 8) * (NHEAD * DV) + jf * 8 + 2 * tg)
                = __floats2half2_rn(oacc[jf][2], oacc[jf][3]);
        }
    }
}

// ---------------------------------------------------------------------------
// Launch
// ---------------------------------------------------------------------------
extern "C" void kernel_launch(void* const* d_in, const int* in_sizes, int n_in,
                              void* d_out, int out_size) {
    const float* q  = (const float*)d_in[0];
    const float* k  = (const float*)d_in[1];
    const float* v  = (const float*)d_in[2];
    const float* Wq = (const float*)d_in[3];
    const float* Wk = (const float*)d_in[4];
    const float* Wv = (const float*)d_in[5];
    const float* Wo = (const float*)d_in[6];
    float* out = (float*)d_out;
    (void)in_sizes; (void)n_in; (void)out_size;

    const int GEMM_SMEM = 4 * 2 * 128 * 40 * 2;                 // 81920 B
    const int ATTN_SMEM = (128 * QLD + 4 * STGA) * 2;           // 92160 B
    cudaFuncSetAttribute(k_proj, cudaFuncAttributeMaxDynamicSharedMemorySize, GEMM_SMEM);
    cudaFuncSetAttribute(k_out,  cudaFuncAttributeMaxDynamicSharedMemorySize, GEMM_SMEM);
    cudaFuncSetAttribute(k_attn, cudaFuncAttributeMaxDynamicSharedMemorySize, ATTN_SMEM);

    k_cvt<<<dim3(4096, 1, 3), 256>>>(q, k, v);
    k_transpose<<<dim3(32, 32, 4), dim3(32, 8)>>>(Wq, Wk, Wv, Wo);
    k_proj<<<dim3(64, 8, 3), 256, GEMM_SMEM>>>();
    k_attn<<<dim3(8, BATCH * NHEAD), 256, ATTN_SMEM>>>(out);
    k_out<<<dim3(64, 8), 256, GEMM_SMEM>>>(out);
}